// round 9
// baseline (speedup 1.0000x reference)
#include <cuda_runtime.h>
#include <cuda_fp16.h>
#include <cstdint>
#include <cstddef>

#define B_ 4
#define T_ 2048
#define D_ 1024

// ---------------------------------------------------------------------------
// Scratch (__device__ globals: allocation-free rule)
// ---------------------------------------------------------------------------
__device__ __half g_xh[(size_t)B_ * T_ * D_];           // x in fp16
__device__ __half g_wt[3][(size_t)D_ * D_];             // W^T fp16 (q,k,v)
__device__ __half g_qkv[3][(size_t)B_ * T_ * D_];       // q,k,v fp16
__device__ __half g_vt[(size_t)B_ * D_ * T_];           // v^T fp16
__device__ __half g_p [(size_t)B_ * T_ * T_];           // E = exp(S) fp16
__device__ float  g_rs[(size_t)B_ * T_];                // row sums of E

__device__ __forceinline__ uint32_t smem_u32(const void* p) {
    uint32_t a;
    asm("{ .reg .u64 t; cvta.to.shared.u64 t, %1; cvt.u32.u64 %0, t; }" : "=r"(a) : "l"(p));
    return a;
}

// 1D bulk async copy gmem->smem, completing on mbarrier (sm_90 PTX)
#define CP_BULK(dst, src, bytes, mbar)                                        \
    asm volatile("cp.async.bulk.shared::cta.global.mbarrier::complete_tx::bytes " \
                 "[%0], [%1], %2, [%3];"                                      \
        :: "r"(dst), "l"(src), "r"(bytes), "r"(mbar) : "memory")

#define MBAR_INIT(a, c)  asm volatile("mbarrier.init.shared.b64 [%0], %1;" :: "r"(a), "r"(c) : "memory")
#define MBAR_EXPECT(a, b) asm volatile("mbarrier.arrive.expect_tx.shared.b64 _, [%0], %1;" :: "r"(a), "r"(b) : "memory")
#define MBAR_WAIT(a, ph) do {                                                            \
    uint32_t _m = (a), _p = (ph), _d;                                                    \
    asm volatile("{ .reg .pred p; mbarrier.try_wait.parity.acquire.cta.shared::cta.b64 " \
                 "p, [%1], %2; selp.b32 %0, 1, 0, p; }" : "=r"(_d) : "r"(_m), "r"(_p) : "memory"); \
    if (!_d) {                                                                           \
        asm volatile("{ .reg .pred P1; WL%=: mbarrier.try_wait.parity.acquire.cta."      \
                     "shared::cta.b64 P1, [%0], %1, 0x989680; @P1 bra.uni WD%=; "        \
                     "bra.uni WL%=; WD%=: }" :: "r"(_m), "r"(_p) : "memory");            \
    }                                                                                    \
} while (0)

#define LDSM_X4(r0, r1, r2, r3, addr)                                        \
    asm volatile("ldmatrix.sync.aligned.m8n8.x4.shared.b16 {%0,%1,%2,%3}, [%4];" \
        : "=r"(r0), "=r"(r1), "=r"(r2), "=r"(r3) : "r"(addr))

// m16n8k16 fp16 mma, fp32 accum
__device__ __forceinline__ void mma_f16(
    float& c0, float& c1, float& c2, float& c3,
    uint32_t a0, uint32_t a1, uint32_t a2, uint32_t a3,
    uint32_t b0, uint32_t b1)
{
    asm volatile(
        "mma.sync.aligned.m16n8k16.row.col.f32.f16.f16.f32 "
        "{%0,%1,%2,%3}, {%4,%5,%6,%7}, {%8,%9}, {%0,%1,%2,%3};"
        : "+f"(c0), "+f"(c1), "+f"(c2), "+f"(c3)
        : "r"(a0), "r"(a1), "r"(a2), "r"(a3), "r"(b0), "r"(b1));
}

// ---------------------------------------------------------------------------
// fp16 tensor GEMM: C[M,N] = A[M,K] @ Bm[N,K]^T (half, K-major rows)
// 128x128x64 block tile, 8 warps (2m x 4n) -> 64x32 warp tiles.
// smem rows padded to 72 halves (144B: 9x16B stride -> conflict-free LDSM).
// 3-stage pipeline loaded with cp.async.bulk (1 row per thread) + mbarrier.
// EXPO: epilogue writes fp16 exp(acc*scale), causal mask, rowsum atomics.
// DIVRS: epilogue divides by rs[row]. KLIM: causal K clip (heavy-first order).
// CSKIP: skip fully-masked tiles.
// ---------------------------------------------------------------------------
constexpr int BM = 128, BN = 128, BK = 64;
constexpr int LDHB = 144;                      // bytes per smem row
constexpr int TILE_BYTES  = BM * LDHB;         // 18432
constexpr int STAGE_BYTES = 2 * TILE_BYTES;    // 36864 (A + B)
constexpr int NSTAGE = 3;
constexpr int SM_STAGE0 = 64;                  // mbarriers live in [0, 24)
constexpr int SMEM_BYTES = SM_STAGE0 + NSTAGE * STAGE_BYTES;  // 110656
constexpr uint32_t ROW_BYTES = BK * 2;         // 128 per bulk copy
constexpr uint32_t WARP_TX = 32 * ROW_BYTES;   // 4096 bytes per warp

template <bool QKV3, bool BIAS, bool EXPO, bool DIVRS, bool CSKIP, bool KLIM, bool OUTH>
__global__ __launch_bounds__(256, 2) void gemm_h(
    const __half* __restrict__ A, const __half* __restrict__ Bm,
    const float* __restrict__ bias0, const float* __restrict__ bias1,
    const float* __restrict__ bias2, void* __restrict__ Cv,
    float* __restrict__ rs,
    int M, int N, int K, float scale, size_t sA, size_t sB, size_t sC)
{
    const int by = KLIM ? ((int)gridDim.y - 1 - (int)blockIdx.y) : (int)blockIdx.y;
    const int m0 = by * BM;
    const int n0 = blockIdx.x * BN;
    if (CSKIP && n0 >= m0 + BM) return;        // fully above causal diagonal

    const int z = blockIdx.z;
    A  += QKV3 ? 0 : (size_t)z * sA;
    Bm += (size_t)z * sB;
    const float* bias = bias0;
    if (QKV3) bias = (z == 0) ? bias0 : (z == 1) ? bias1 : bias2;

    int Keff = K;
    if (KLIM) { int lim = m0 + BM; Keff = lim < K ? lim : K; }
    const int KT = Keff / BK;

    extern __shared__ char sm[];
    const uint32_t sm_b = smem_u32(sm);

    const int tid = threadIdx.x;
    const int wid = tid >> 5;
    const int lid = tid & 31;
    const int wm = wid >> 2;                   // 0..1
    const int wn = wid & 3;                    // 0..3
    const int g  = lid >> 2;                   // 0..7
    const int t4 = lid & 3;                    // 0..3

    // mbarrier init: one per stage, 8 arrives (one expect_tx per warp)
    if (tid == 0) {
#pragma unroll
        for (int s = 0; s < NSTAGE; s++) MBAR_INIT(sm_b + s * 8, 8);
    }
    __syncthreads();

    // My row for bulk loading: tid<128 -> A row tid; else B row tid-128.
    const int lrowA = (tid < BM);
    const int myrow = lrowA ? tid : (tid - BM);

    // Stage loader: per-warp expect_tx, then one 128B bulk per thread.
    auto load_stage = [&](int stage, int kt) {
        const uint32_t mb = sm_b + stage * 8;
        if (lid == 0) MBAR_EXPECT(mb, WARP_TX);
        __syncwarp();
        const uint32_t base = sm_b + SM_STAGE0 + stage * STAGE_BYTES
                              + (lrowA ? 0u : (uint32_t)TILE_BYTES)
                              + (uint32_t)myrow * LDHB;
        const __half* src = (lrowA ? A + (size_t)(m0 + myrow) * K
                                   : Bm + (size_t)(n0 + myrow) * K)
                            + (size_t)kt * BK;
        CP_BULK(base, src, ROW_BYTES, mb);
    };

    load_stage(0, 0);
    if (KT > 1) load_stage(1, 1);

    // LDSM per-lane address pieces
    const int fr = lid & 15;
    const uint32_t lk = (lid & 16) ? 16u : 0u;
    const uint32_t aoff = SM_STAGE0 + (uint32_t)((wm * 64 + fr) * LDHB) + lk;
    const uint32_t boff = SM_STAGE0 + TILE_BYTES + (uint32_t)((wn * 32 + fr) * LDHB) + lk;

    float acc[4][4][4];
#pragma unroll
    for (int i = 0; i < 4; i++)
#pragma unroll
        for (int j = 0; j < 4; j++)
#pragma unroll
            for (int r = 0; r < 4; r++) acc[i][j][r] = 0.f;

    int stage = 0;
    for (int kt = 0; kt < KT; kt++) {
        // stage ready?
        MBAR_WAIT(sm_b + stage * 8, (uint32_t)((kt / NSTAGE) & 1));
        __syncthreads();   // all warps done with stage (kt-1)%3 == (kt+2)%3

        if (kt + 2 < KT) {
            int ns = stage + 2; if (ns >= NSTAGE) ns -= NSTAGE;
            load_stage(ns, kt + 2);
        }

        const uint32_t Sb = sm_b + stage * STAGE_BYTES;

#pragma unroll
        for (int s = 0; s < 4; s++) {          // 4 x k16 steps
            uint32_t a[4][4], b[2][4];
#pragma unroll
            for (int mt = 0; mt < 4; mt++)
                LDSM_X4(a[mt][0], a[mt][1], a[mt][2], a[mt][3],
                        Sb + aoff + mt * (16 * LDHB) + s * 32);
#pragma unroll
            for (int p = 0; p < 2; p++)
                LDSM_X4(b[p][0], b[p][1], b[p][2], b[p][3],
                        Sb + boff + p * (16 * LDHB) + s * 32);
#pragma unroll
            for (int mt = 0; mt < 4; mt++)
#pragma unroll
                for (int nt = 0; nt < 4; nt++) {
                    const int p = nt >> 1, o = nt & 1;
                    mma_f16(acc[mt][nt][0], acc[mt][nt][1],
                            acc[mt][nt][2], acc[mt][nt][3],
                            a[mt][0], a[mt][1], a[mt][2], a[mt][3],
                            b[p][o], b[p][2 + o]);
                }
        }
        stage++; if (stage >= NSTAGE) stage = 0;
    }

    const bool diag = EXPO && (m0 == n0);

    // Epilogue: c0,c1 -> (row g, cols 2t4,2t4+1); c2,c3 -> row g+8.
#pragma unroll
    for (int mt = 0; mt < 4; mt++) {
        const int mr = m0 + wm * 64 + mt * 16 + g;
        float rsum0 = 0.f, rsum1 = 0.f;
        float ia = 1.f, ib = 1.f;
        if (DIVRS) {
            ia = 1.0f / __ldg(rs + (size_t)z * T_ + mr);
            ib = 1.0f / __ldg(rs + (size_t)z * T_ + mr + 8);
        }
#pragma unroll
        for (int nt = 0; nt < 4; nt++) {
            const int nc = n0 + wn * 32 + nt * 8 + 2 * t4;
            float f0 = acc[mt][nt][0], f1 = acc[mt][nt][1];
            float f2 = acc[mt][nt][2], f3 = acc[mt][nt][3];
            if (BIAS) {
                float b0 = __ldg(bias + nc), b1 = __ldg(bias + nc + 1);
                f0 += b0; f1 += b1; f2 += b0; f3 += b1;
            }
            if (EXPO) {
                float e0 = __expf(f0 * scale), e1 = __expf(f1 * scale);
                float e2 = __expf(f2 * scale), e3 = __expf(f3 * scale);
                if (diag) {
                    if (nc     > mr    ) e0 = 0.f;
                    if (nc + 1 > mr    ) e1 = 0.f;
                    if (nc     > mr + 8) e2 = 0.f;
                    if (nc + 1 > mr + 8) e3 = 0.f;
                }
                __half2 h0 = __floats2half2_rn(e0, e1);
                __half2 h1 = __floats2half2_rn(e2, e3);
                float2 r0 = __half22float2(h0), r1 = __half22float2(h1);
                rsum0 += r0.x + r0.y;
                rsum1 += r1.x + r1.y;
                __half* C = (__half*)Cv + (size_t)z * sC;
                *(__half2*)(C + (size_t)mr * N + nc)       = h0;
                *(__half2*)(C + (size_t)(mr + 8) * N + nc) = h1;
            } else if (OUTH) {
                __half* C = (__half*)Cv + (size_t)z * sC;
                *(__half2*)(C + (size_t)mr * N + nc)       = __floats2half2_rn(f0, f1);
                *(__half2*)(C + (size_t)(mr + 8) * N + nc) = __floats2half2_rn(f2, f3);
            } else {
                if (DIVRS) { f0 *= ia; f1 *= ia; f2 *= ib; f3 *= ib; }
                float* C = (float*)Cv + (size_t)z * sC;
                *(float2*)(C + (size_t)mr * N + nc)       = make_float2(f0, f1);
                *(float2*)(C + (size_t)(mr + 8) * N + nc) = make_float2(f2, f3);
            }
        }
        if (EXPO) {
            rsum0 += __shfl_xor_sync(0xffffffffu, rsum0, 1);
            rsum0 += __shfl_xor_sync(0xffffffffu, rsum0, 2);
            rsum1 += __shfl_xor_sync(0xffffffffu, rsum1, 1);
            rsum1 += __shfl_xor_sync(0xffffffffu, rsum1, 2);
            if (t4 == 0) {
                atomicAdd(rs + (size_t)z * T_ + mr,     rsum0);
                atomicAdd(rs + (size_t)z * T_ + mr + 8, rsum1);
            }
        }
    }
}

// ---------------------------------------------------------------------------
// fp32 -> fp16 convert (x)
// ---------------------------------------------------------------------------
__global__ void f2h_kernel(const float* __restrict__ src, __half* __restrict__ dst, int n8)
{
    int i = blockIdx.x * blockDim.x + threadIdx.x;
    if (i >= n8) return;
    float4 v0 = ((const float4*)src)[2 * i];
    float4 v1 = ((const float4*)src)[2 * i + 1];
    __half2 h[4];
    h[0] = __floats2half2_rn(v0.x, v0.y);
    h[1] = __floats2half2_rn(v0.z, v0.w);
    h[2] = __floats2half2_rn(v1.x, v1.y);
    h[3] = __floats2half2_rn(v1.z, v1.w);
    ((uint4*)dst)[i] = *(uint4*)h;
}

// ---------------------------------------------------------------------------
// Zero the row-sum accumulator
// ---------------------------------------------------------------------------
__global__ void zero_rs_kernel(float* __restrict__ rs, int n)
{
    int i = blockIdx.x * blockDim.x + threadIdx.x;
    if (i < n) rs[i] = 0.f;
}

// ---------------------------------------------------------------------------
// Transpose fp32 -> fp16 for the three weight matrices (z selects q/k/v)
// ---------------------------------------------------------------------------
__global__ void transpose_f2h3(const float* __restrict__ W0, const float* __restrict__ W1,
                               const float* __restrict__ W2, __half* __restrict__ dst,
                               int R, int Ccols, size_t sDst)
{
    const float* src = (blockIdx.z == 0) ? W0 : (blockIdx.z == 1) ? W1 : W2;
    __half* d = dst + (size_t)blockIdx.z * sDst;
    __shared__ float t[32][33];
    const int r0 = blockIdx.y * 32, c0 = blockIdx.x * 32;
#pragma unroll
    for (int i = 0; i < 4; i++) {
        int r = r0 + threadIdx.y + i * 8;
        t[threadIdx.y + i * 8][threadIdx.x] = src[(size_t)r * Ccols + c0 + threadIdx.x];
    }
    __syncthreads();
#pragma unroll
    for (int i = 0; i < 4; i++) {
        int c = c0 + threadIdx.y + i * 8;
        d[(size_t)c * R + r0 + threadIdx.x] =
            __float2half_rn(t[threadIdx.x][threadIdx.y + i * 8]);
    }
}

// ---------------------------------------------------------------------------
// Transpose fp16 -> fp16: dst[c, r] = src[r, c]; batched via blockIdx.z
// ---------------------------------------------------------------------------
__global__ void transpose_h2h(const __half* __restrict__ src, __half* __restrict__ dst,
                              int R, int Ccols, size_t sSrc, size_t sDst)
{
    src += (size_t)blockIdx.z * sSrc;
    dst += (size_t)blockIdx.z * sDst;
    __shared__ __half t[32][34];
    const int r0 = blockIdx.y * 32, c0 = blockIdx.x * 32;
#pragma unroll
    for (int i = 0; i < 4; i++) {
        int r = r0 + threadIdx.y + i * 8;
        t[threadIdx.y + i * 8][threadIdx.x] = src[(size_t)r * Ccols + c0 + threadIdx.x];
    }
    __syncthreads();
#pragma unroll
    for (int i = 0; i < 4; i++) {
        int c = c0 + threadIdx.y + i * 8;
        dst[(size_t)c * R + r0 + threadIdx.x] = t[threadIdx.x][threadIdx.y + i * 8];
    }
}

// ---------------------------------------------------------------------------
extern "C" void kernel_launch(void* const* d_in, const int* in_sizes, int n_in,
                              void* d_out, int out_size)
{
    const float* x  = (const float*)d_in[0];
    const float* Wq = (const float*)d_in[1];
    const float* bq = (const float*)d_in[2];
    const float* Wk = (const float*)d_in[3];
    const float* bk = (const float*)d_in[4];
    const float* Wv = (const float*)d_in[5];
    const float* bv = (const float*)d_in[6];
    float* out = (float*)d_out;

    __half *xh, *wt, *qkv, *vt, *p;
    float *rs;
    cudaGetSymbolAddress((void**)&xh,  g_xh);
    cudaGetSymbolAddress((void**)&wt,  g_wt);
    cudaGetSymbolAddress((void**)&qkv, g_qkv);
    cudaGetSymbolAddress((void**)&vt,  g_vt);
    cudaGetSymbolAddress((void**)&p,   g_p);
    cudaGetSymbolAddress((void**)&rs,  g_rs);

    const int M = B_ * T_;               // 8192
    const size_t TD = (size_t)T_ * D_;
    const size_t TT = (size_t)T_ * T_;
    const size_t DD = (size_t)D_ * D_;
    __half* q = qkv;
    __half* k = qkv + (size_t)M * D_;
    __half* v = qkv + 2 * (size_t)M * D_;

    cudaFuncSetAttribute(gemm_h<true,  true,  false, false, false, false, true >, cudaFuncAttributeMaxDynamicSharedMemorySize, SMEM_BYTES);
    cudaFuncSetAttribute(gemm_h<false, false, true,  false, true,  false, true >, cudaFuncAttributeMaxDynamicSharedMemorySize, SMEM_BYTES);
    cudaFuncSetAttribute(gemm_h<false, false, false, true,  false, true,  false>, cudaFuncAttributeMaxDynamicSharedMemorySize, SMEM_BYTES);

    // 0) x -> fp16; W -> W^T fp16 (single launch); zero rs
    f2h_kernel<<<(M * D_ / 8 + 255) / 256, 256>>>(x, xh, M * D_ / 8);
    zero_rs_kernel<<<(B_ * T_ + 255) / 256, 256>>>(rs, B_ * T_);
    transpose_f2h3<<<dim3(D_ / 32, D_ / 32, 3), dim3(32, 8)>>>(Wq, Wk, Wv, wt, D_, D_, DD);

    // 1) fused QKV projections (one launch, z selects q/k/v), fp16 out
    dim3 gProj(D_ / BN, M / BM, 3);
    gemm_h<true, true, false, false, false, false, true><<<gProj, 256, SMEM_BYTES>>>(
        xh, wt, bq, bk, bv, qkv, nullptr, M, D_, D_, 1.f, 0, DD, (size_t)M * D_);

    // 2) v^T (per batch), fp16
    transpose_h2h<<<dim3(D_ / 32, T_ / 32, B_), dim3(32, 8)>>>(v, vt, T_, D_, TD, TD);

    // 3) E = exp(Q K^T / 32) fp16 (lower-triangle tiles only, diagonal masked),
    //    row sums accumulated into rs via atomics.
    dim3 gS(T_ / BN, T_ / BM, B_);
    gemm_h<false, false, true, false, true, false, true><<<gS, 256, SMEM_BYTES>>>(
        q, k, nullptr, nullptr, nullptr, p, rs, T_, T_, D_, 1.0f / 32.0f, TD, TD, TT);

    // 4) out = (E @ V) / rs with causal K-limit, heavy-first m order, fp32 out
    dim3 gPV(D_ / BN, T_ / BM, B_);
    gemm_h<false, false, false, true, false, true, false><<<gPV, 256, SMEM_BYTES>>>(
        p, vt, nullptr, nullptr, nullptr, out, rs, T_, D_, T_, 1.f, TT, TD, TD);
}

// round 10
// speedup vs baseline: 1.1190x; 1.1190x over previous
#include <cuda_runtime.h>
#include <cuda_fp16.h>
#include <cstdint>
#include <cstddef>

#define B_ 4
#define T_ 2048
#define D_ 1024

// ---------------------------------------------------------------------------
// Scratch (__device__ globals: allocation-free rule)
// ---------------------------------------------------------------------------
__device__ __half g_xh[(size_t)B_ * T_ * D_];           // x in fp16
__device__ __half g_wt[3][(size_t)D_ * D_];             // W^T fp16 (q,k,v)
__device__ __half g_qkv[3][(size_t)B_ * T_ * D_];       // q,k,v fp16
__device__ __half g_vt[(size_t)B_ * D_ * T_];           // v^T fp16
__device__ __half g_p [(size_t)B_ * T_ * T_];           // E = exp(S) fp16
__device__ float  g_rs[(size_t)B_ * T_];                // row sums of E

#define CP_ASYNC16(dst, src) \
    asm volatile("cp.async.cg.shared.global [%0], [%1], 16;" :: "r"(dst), "l"(src) : "memory")
#define CP_COMMIT()  asm volatile("cp.async.commit_group;" ::: "memory")
#define CP_WAIT1()   asm volatile("cp.async.wait_group 1;" ::: "memory")
#define CP_WAIT0()   asm volatile("cp.async.wait_group 0;" ::: "memory")

__device__ __forceinline__ uint32_t smem_u32(const void* p) {
    uint32_t a;
    asm("{ .reg .u64 t; cvta.to.shared.u64 t, %1; cvt.u32.u64 %0, t; }" : "=r"(a) : "l"(p));
    return a;
}

#define LDSM_X4(r0, r1, r2, r3, addr)                                        \
    asm volatile("ldmatrix.sync.aligned.m8n8.x4.shared.b16 {%0,%1,%2,%3}, [%4];" \
        : "=r"(r0), "=r"(r1), "=r"(r2), "=r"(r3) : "r"(addr))

// m16n8k16 fp16 mma, fp32 accum
__device__ __forceinline__ void mma_f16(
    float& c0, float& c1, float& c2, float& c3,
    uint32_t a0, uint32_t a1, uint32_t a2, uint32_t a3,
    uint32_t b0, uint32_t b1)
{
    asm volatile(
        "mma.sync.aligned.m16n8k16.row.col.f32.f16.f16.f32 "
        "{%0,%1,%2,%3}, {%4,%5,%6,%7}, {%8,%9}, {%0,%1,%2,%3};"
        : "+f"(c0), "+f"(c1), "+f"(c2), "+f"(c3)
        : "r"(a0), "r"(a1), "r"(a2), "r"(a3), "r"(b0), "r"(b1));
}

// ---------------------------------------------------------------------------
// fp16 tensor GEMM: C[M,N] = A[M,K] @ Bm[N,K]^T (half, K-major rows)
// 128x128x64 block tile, 4 warps (2m x 2n) -> 64x64 warp tiles (128 threads).
// smem rows padded to 72 halves (144B: 9x16B stride -> conflict-free LDSM).
// 3-stage cp.async pipeline, 2 CTAs/SM.
// EXPO: epilogue writes fp16 exp(acc*scale), causal mask, rowsum atomics.
// DIVRS: epilogue divides by rs[row]. KLIM: causal K clip (heavy-first order).
// CSKIP: skip fully-masked tiles.
// ---------------------------------------------------------------------------
constexpr int BM = 128, BN = 128, BK = 64;
constexpr int NTHR = 128;
constexpr int LDHB = 144;                      // bytes per smem row
constexpr int TILE_BYTES  = BM * LDHB;         // 18432
constexpr int STAGE_BYTES = 2 * TILE_BYTES;    // 36864 (A + B)
constexpr int NSTAGE = 3;
constexpr int SMEM_BYTES = NSTAGE * STAGE_BYTES;  // 110592

template <bool QKV3, bool BIAS, bool EXPO, bool DIVRS, bool CSKIP, bool KLIM, bool OUTH>
__global__ __launch_bounds__(NTHR, 2) void gemm_h(
    const __half* __restrict__ A, const __half* __restrict__ Bm,
    const float* __restrict__ bias0, const float* __restrict__ bias1,
    const float* __restrict__ bias2, void* __restrict__ Cv,
    float* __restrict__ rs,
    int M, int N, int K, float scale, size_t sA, size_t sB, size_t sC)
{
    const int by = KLIM ? ((int)gridDim.y - 1 - (int)blockIdx.y) : (int)blockIdx.y;
    const int m0 = by * BM;
    const int n0 = blockIdx.x * BN;
    if (CSKIP && n0 >= m0 + BM) return;        // fully above causal diagonal

    const int z = blockIdx.z;
    A  += QKV3 ? 0 : (size_t)z * sA;
    Bm += (size_t)z * sB;
    const float* bias = bias0;
    if (QKV3) bias = (z == 0) ? bias0 : (z == 1) ? bias1 : bias2;

    int Keff = K;
    if (KLIM) { int lim = m0 + BM; Keff = lim < K ? lim : K; }
    const int KT = Keff / BK;

    extern __shared__ char sm[];
    const uint32_t sm_b = smem_u32(sm);

    const int tid = threadIdx.x;
    const int wid = tid >> 5;
    const int lid = tid & 31;
    const int wm = wid >> 1;                   // 0..1
    const int wn = wid & 1;                    // 0..1
    const int g  = lid >> 2;                   // 0..7
    const int t4 = lid & 3;                    // 0..3

    // Stage loader: A 128x64h + B 128x64h; 16B chunks, 16 per thread.
    auto load_stage = [&](int stage, int kt) {
        const uint32_t ab = sm_b + stage * STAGE_BYTES;
        const uint32_t bbs = ab + TILE_BYTES;
        const __half* Ag = A + (size_t)m0 * K + kt * BK;
        const __half* Bg = Bm + (size_t)n0 * K + kt * BK;
#pragma unroll
        for (int i = 0; i < 8; i++) {
            int idx = i * NTHR + tid;          // 0..1023
            int row = idx >> 3, c = idx & 7;
            uint32_t off = (uint32_t)(row * LDHB + c * 16);
            CP_ASYNC16(ab + off,  Ag + (size_t)row * K + c * 8);
            CP_ASYNC16(bbs + off, Bg + (size_t)row * K + c * 8);
        }
    };

    load_stage(0, 0);
    CP_COMMIT();
    if (KT > 1) { load_stage(1, 1); CP_COMMIT(); }

    // LDSM per-lane address pieces: lanes 0-15 -> rows, lanes 16-31 -> +16B (k+8)
    const int fr = lid & 15;
    const uint32_t lk = (lid & 16) ? 16u : 0u;
    const uint32_t aoff = (uint32_t)((wm * 64 + fr) * LDHB) + lk;
    const uint32_t boff = (uint32_t)(TILE_BYTES + (wn * 64 + fr) * LDHB) + lk;

    float acc[4][8][4];
#pragma unroll
    for (int i = 0; i < 4; i++)
#pragma unroll
        for (int j = 0; j < 8; j++)
#pragma unroll
            for (int r = 0; r < 4; r++) acc[i][j][r] = 0.f;

    int stage = 0;
    for (int kt = 0; kt < KT; kt++) {
        if (kt + 1 < KT) CP_WAIT1(); else CP_WAIT0();
        __syncthreads();

        if (kt + 2 < KT) {
            int ns = stage + 2; if (ns >= NSTAGE) ns -= NSTAGE;
            load_stage(ns, kt + 2);
            CP_COMMIT();
        }

        const uint32_t Sb = sm_b + stage * STAGE_BYTES;

#pragma unroll
        for (int s = 0; s < 4; s++) {          // 4 x k16 steps
            uint32_t a[4][4], b[4][4];
#pragma unroll
            for (int mt = 0; mt < 4; mt++)
                LDSM_X4(a[mt][0], a[mt][1], a[mt][2], a[mt][3],
                        Sb + aoff + mt * (16 * LDHB) + s * 32);
#pragma unroll
            for (int p = 0; p < 4; p++)
                LDSM_X4(b[p][0], b[p][1], b[p][2], b[p][3],
                        Sb + boff + p * (16 * LDHB) + s * 32);
#pragma unroll
            for (int mt = 0; mt < 4; mt++)
#pragma unroll
                for (int nt = 0; nt < 8; nt++) {
                    const int p = nt >> 1, o = nt & 1;
                    mma_f16(acc[mt][nt][0], acc[mt][nt][1],
                            acc[mt][nt][2], acc[mt][nt][3],
                            a[mt][0], a[mt][1], a[mt][2], a[mt][3],
                            b[p][o], b[p][2 + o]);
                }
        }
        stage++; if (stage >= NSTAGE) stage = 0;
    }

    const bool diag = EXPO && (m0 == n0);

    // Epilogue: c0,c1 -> (row g, cols 2t4,2t4+1); c2,c3 -> row g+8.
#pragma unroll
    for (int mt = 0; mt < 4; mt++) {
        const int mr = m0 + wm * 64 + mt * 16 + g;
        float rsum0 = 0.f, rsum1 = 0.f;
        float ia = 1.f, ib = 1.f;
        if (DIVRS) {
            ia = 1.0f / __ldg(rs + (size_t)z * T_ + mr);
            ib = 1.0f / __ldg(rs + (size_t)z * T_ + mr + 8);
        }
#pragma unroll
        for (int nt = 0; nt < 8; nt++) {
            const int nc = n0 + wn * 64 + nt * 8 + 2 * t4;
            float f0 = acc[mt][nt][0], f1 = acc[mt][nt][1];
            float f2 = acc[mt][nt][2], f3 = acc[mt][nt][3];
            if (BIAS) {
                float b0 = __ldg(bias + nc), b1 = __ldg(bias + nc + 1);
                f0 += b0; f1 += b1; f2 += b0; f3 += b1;
            }
            if (EXPO) {
                float e0 = __expf(f0 * scale), e1 = __expf(f1 * scale);
                float e2 = __expf(f2 * scale), e3 = __expf(f3 * scale);
                if (diag) {
                    if (nc     > mr    ) e0 = 0.f;
                    if (nc + 1 > mr    ) e1 = 0.f;
                    if (nc     > mr + 8) e2 = 0.f;
                    if (nc + 1 > mr + 8) e3 = 0.f;
                }
                __half2 h0 = __floats2half2_rn(e0, e1);
                __half2 h1 = __floats2half2_rn(e2, e3);
                float2 r0 = __half22float2(h0), r1 = __half22float2(h1);
                rsum0 += r0.x + r0.y;
                rsum1 += r1.x + r1.y;
                __half* C = (__half*)Cv + (size_t)z * sC;
                *(__half2*)(C + (size_t)mr * N + nc)       = h0;
                *(__half2*)(C + (size_t)(mr + 8) * N + nc) = h1;
            } else if (OUTH) {
                __half* C = (__half*)Cv + (size_t)z * sC;
                *(__half2*)(C + (size_t)mr * N + nc)       = __floats2half2_rn(f0, f1);
                *(__half2*)(C + (size_t)(mr + 8) * N + nc) = __floats2half2_rn(f2, f3);
            } else {
                if (DIVRS) { f0 *= ia; f1 *= ia; f2 *= ib; f3 *= ib; }
                float* C = (float*)Cv + (size_t)z * sC;
                *(float2*)(C + (size_t)mr * N + nc)       = make_float2(f0, f1);
                *(float2*)(C + (size_t)(mr + 8) * N + nc) = make_float2(f2, f3);
            }
        }
        if (EXPO) {
            rsum0 += __shfl_xor_sync(0xffffffffu, rsum0, 1);
            rsum0 += __shfl_xor_sync(0xffffffffu, rsum0, 2);
            rsum1 += __shfl_xor_sync(0xffffffffu, rsum1, 1);
            rsum1 += __shfl_xor_sync(0xffffffffu, rsum1, 2);
            if (t4 == 0) {
                atomicAdd(rs + (size_t)z * T_ + mr,     rsum0);
                atomicAdd(rs + (size_t)z * T_ + mr + 8, rsum1);
            }
        }
    }
}

// ---------------------------------------------------------------------------
// fp32 -> fp16 convert (x)
// ---------------------------------------------------------------------------
__global__ void f2h_kernel(const float* __restrict__ src, __half* __restrict__ dst, int n8)
{
    int i = blockIdx.x * blockDim.x + threadIdx.x;
    if (i >= n8) return;
    float4 v0 = ((const float4*)src)[2 * i];
    float4 v1 = ((const float4*)src)[2 * i + 1];
    __half2 h[4];
    h[0] = __floats2half2_rn(v0.x, v0.y);
    h[1] = __floats2half2_rn(v0.z, v0.w);
    h[2] = __floats2half2_rn(v1.x, v1.y);
    h[3] = __floats2half2_rn(v1.z, v1.w);
    ((uint4*)dst)[i] = *(uint4*)h;
}

// ---------------------------------------------------------------------------
// Zero the row-sum accumulator
// ---------------------------------------------------------------------------
__global__ void zero_rs_kernel(float* __restrict__ rs, int n)
{
    int i = blockIdx.x * blockDim.x + threadIdx.x;
    if (i < n) rs[i] = 0.f;
}

// ---------------------------------------------------------------------------
// Transpose fp32 -> fp16 for the three weight matrices (z selects q/k/v)
// ---------------------------------------------------------------------------
__global__ void transpose_f2h3(const float* __restrict__ W0, const float* __restrict__ W1,
                               const float* __restrict__ W2, __half* __restrict__ dst,
                               int R, int Ccols, size_t sDst)
{
    const float* src = (blockIdx.z == 0) ? W0 : (blockIdx.z == 1) ? W1 : W2;
    __half* d = dst + (size_t)blockIdx.z * sDst;
    __shared__ float t[32][33];
    const int r0 = blockIdx.y * 32, c0 = blockIdx.x * 32;
#pragma unroll
    for (int i = 0; i < 4; i++) {
        int r = r0 + threadIdx.y + i * 8;
        t[threadIdx.y + i * 8][threadIdx.x] = src[(size_t)r * Ccols + c0 + threadIdx.x];
    }
    __syncthreads();
#pragma unroll
    for (int i = 0; i < 4; i++) {
        int c = c0 + threadIdx.y + i * 8;
        d[(size_t)c * R + r0 + threadIdx.x] =
            __float2half_rn(t[threadIdx.x][threadIdx.y + i * 8]);
    }
}

// ---------------------------------------------------------------------------
// Transpose fp16 -> fp16: dst[c, r] = src[r, c]; batched via blockIdx.z
// ---------------------------------------------------------------------------
__global__ void transpose_h2h(const __half* __restrict__ src, __half* __restrict__ dst,
                              int R, int Ccols, size_t sSrc, size_t sDst)
{
    src += (size_t)blockIdx.z * sSrc;
    dst += (size_t)blockIdx.z * sDst;
    __shared__ __half t[32][34];
    const int r0 = blockIdx.y * 32, c0 = blockIdx.x * 32;
#pragma unroll
    for (int i = 0; i < 4; i++) {
        int r = r0 + threadIdx.y + i * 8;
        t[threadIdx.y + i * 8][threadIdx.x] = src[(size_t)r * Ccols + c0 + threadIdx.x];
    }
    __syncthreads();
#pragma unroll
    for (int i = 0; i < 4; i++) {
        int c = c0 + threadIdx.y + i * 8;
        dst[(size_t)c * R + r0 + threadIdx.x] = t[threadIdx.x][threadIdx.y + i * 8];
    }
}

// ---------------------------------------------------------------------------
extern "C" void kernel_launch(void* const* d_in, const int* in_sizes, int n_in,
                              void* d_out, int out_size)
{
    const float* x  = (const float*)d_in[0];
    const float* Wq = (const float*)d_in[1];
    const float* bq = (const float*)d_in[2];
    const float* Wk = (const float*)d_in[3];
    const float* bk = (const float*)d_in[4];
    const float* Wv = (const float*)d_in[5];
    const float* bv = (const float*)d_in[6];
    float* out = (float*)d_out;

    __half *xh, *wt, *qkv, *vt, *p;
    float *rs;
    cudaGetSymbolAddress((void**)&xh,  g_xh);
    cudaGetSymbolAddress((void**)&wt,  g_wt);
    cudaGetSymbolAddress((void**)&qkv, g_qkv);
    cudaGetSymbolAddress((void**)&vt,  g_vt);
    cudaGetSymbolAddress((void**)&p,   g_p);
    cudaGetSymbolAddress((void**)&rs,  g_rs);

    const int M = B_ * T_;               // 8192
    const size_t TD = (size_t)T_ * D_;
    const size_t TT = (size_t)T_ * T_;
    const size_t DD = (size_t)D_ * D_;
    __half* q = qkv;
    __half* k = qkv + (size_t)M * D_;
    __half* v = qkv + 2 * (size_t)M * D_;

    cudaFuncSetAttribute(gemm_h<true,  true,  false, false, false, false, true >, cudaFuncAttributeMaxDynamicSharedMemorySize, SMEM_BYTES);
    cudaFuncSetAttribute(gemm_h<false, false, true,  false, true,  false, true >, cudaFuncAttributeMaxDynamicSharedMemorySize, SMEM_BYTES);
    cudaFuncSetAttribute(gemm_h<false, false, false, true,  false, true,  false>, cudaFuncAttributeMaxDynamicSharedMemorySize, SMEM_BYTES);

    // 0) x -> fp16; W -> W^T fp16 (single launch); zero rs
    f2h_kernel<<<(M * D_ / 8 + 255) / 256, 256>>>(x, xh, M * D_ / 8);
    zero_rs_kernel<<<(B_ * T_ + 255) / 256, 256>>>(rs, B_ * T_);
    transpose_f2h3<<<dim3(D_ / 32, D_ / 32, 3), dim3(32, 8)>>>(Wq, Wk, Wv, wt, D_, D_, DD);

    // 1) fused QKV projections (one launch, z selects q/k/v), fp16 out
    dim3 gProj(D_ / BN, M / BM, 3);
    gemm_h<true, true, false, false, false, false, true><<<gProj, NTHR, SMEM_BYTES>>>(
        xh, wt, bq, bk, bv, qkv, nullptr, M, D_, D_, 1.f, 0, DD, (size_t)M * D_);

    // 2) v^T (per batch), fp16
    transpose_h2h<<<dim3(D_ / 32, T_ / 32, B_), dim3(32, 8)>>>(v, vt, T_, D_, TD, TD);

    // 3) E = exp(Q K^T / 32) fp16 (lower-triangle tiles only, diagonal masked),
    //    row sums accumulated into rs via atomics.
    dim3 gS(T_ / BN, T_ / BM, B_);
    gemm_h<false, false, true, false, true, false, true><<<gS, NTHR, SMEM_BYTES>>>(
        q, k, nullptr, nullptr, nullptr, p, rs, T_, T_, D_, 1.0f / 32.0f, TD, TD, TT);

    // 4) out = (E @ V) / rs with causal K-limit, heavy-first m order, fp32 out
    dim3 gPV(D_ / BN, T_ / BM, B_);
    gemm_h<false, false, false, true, false, true, false><<<gPV, NTHR, SMEM_BYTES>>>(
        p, vt, nullptr, nullptr, nullptr, out, rs, T_, D_, T_, 1.f, TT, TD, TD);
}